// round 14
// baseline (speedup 1.0000x reference)
#include <cuda_runtime.h>
#include <cstdint>

#define NN    100000
#define DD    512
#define EPSBN 1e-5f

// smem: 2 buffers x (A 128x36 + B 128x36) floats
#define SA        36
#define BUF_FL    (128 * SA)
#define SMEM_FL   (4 * BUF_FL)
#define SMEM_BYTES (SMEM_FL * 4)

// ---------------- scratch (static device globals; no allocation) ----------
__device__ float g_t1[(size_t)NN * DD];
__device__ float g_t2[(size_t)NN * DD];
__device__ float g_deg[NN];
__device__ float g_dinv[NN];
__device__ float g_s[NN];
__device__ float g_colsum[2 * DD];
__device__ float g_colsq[2 * DD];
__device__ float g_mu[2 * DD];
__device__ float g_rs[2 * DD];

// ---------------- helpers ---------------------------------------------------
__device__ __forceinline__ float to_tf32(float x) {
    float r;
    asm("cvt.rna.tf32.f32 %0, %1;" : "=f"(r) : "f"(x));
    return r;
}
__device__ __forceinline__ void mma1688(float* c, const uint32_t* a, const uint32_t* b) {
    asm volatile(
        "mma.sync.aligned.m16n8k8.row.col.f32.tf32.tf32.f32 "
        "{%0,%1,%2,%3}, {%4,%5,%6,%7}, {%8,%9}, {%0,%1,%2,%3};"
        : "+f"(c[0]), "+f"(c[1]), "+f"(c[2]), "+f"(c[3])
        : "r"(a[0]), "r"(a[1]), "r"(a[2]), "r"(a[3]), "r"(b[0]), "r"(b[1]));
}

// ---------------- graph-scale kernels -------------------------------------
__global__ void k_init() {
    int i = blockIdx.x * blockDim.x + threadIdx.x;
    if (i < NN) g_deg[i] = 1.0f;
    if (i < 2 * DD) { g_colsum[i] = 0.f; g_colsq[i] = 0.f; }
}
__global__ void k_deg(const int* __restrict__ ei, int E) {
    int e = blockIdx.x * blockDim.x + threadIdx.x;
    if (e >= E) return;
    int s = ei[e], d = ei[E + e];
    if (s != d) atomicAdd(&g_deg[d], 1.0f);
}
__global__ void k_dinv() {
    int i = blockIdx.x * blockDim.x + threadIdx.x;
    if (i < NN) {
        float dg = g_deg[i];
        g_dinv[i] = rsqrtf(dg);
        g_s[i] = 1.0f / dg;
    }
}
__global__ void k_s(const int* __restrict__ ei, int E) {
    int e = blockIdx.x * blockDim.x + threadIdx.x;
    if (e >= E) return;
    int s = ei[e], d = ei[E + e];
    if (s != d) atomicAdd(&g_s[s], g_dinv[s] * g_dinv[d]);
}
__global__ void k_bnstat(int layer) {
    int c = threadIdx.x;
    float mu  = g_colsum[layer * DD + c] * (1.0f / NN);
    float var = g_colsq[layer * DD + c] * (1.0f / NN) - mu * mu;
    g_mu[layer * DD + c] = mu;
    g_rs[layer * DD + c] = rsqrtf(var + EPSBN);
}

// ---------------- tf32 mma.sync fused GEMM ---------------------------------
// Y[NN,512] = BNrelu?(A) @ W^T * s + b ; optional column sum/sumsq stats.
// CTA 128x128, K-chunk 32, double-buffered smem, 8 warps (2M x 4N), warp 64x32.
template <int BN_IN, int STATS>
__global__ void __launch_bounds__(256, 1)
k_gemm(const float* __restrict__ A, const float* __restrict__ W,
       const float* __restrict__ bias, float* __restrict__ Y,
       const float* __restrict__ mu, const float* __restrict__ rs,
       float* __restrict__ colsum, float* __restrict__ colsq)
{
    extern __shared__ float smem[];
    // buffer p: A at p*BUF_FL, B at 2*BUF_FL + p*BUF_FL

    const int tid  = threadIdx.x;
    const int lane = tid & 31;
    const int warpId = tid >> 5;
    const int warpM = warpId & 1;        // 0..1  (64-row band)
    const int warpN = warpId >> 1;       // 0..3  (32-col band)
    const int grp = lane >> 2;           // 0..7
    const int qd  = lane & 3;            // 0..3
    const int rowBase = blockIdx.y * 128;
    const int colBase = blockIdx.x * 128;

    float acc[4][4][4];
    #pragma unroll
    for (int m = 0; m < 4; m++)
        #pragma unroll
        for (int n = 0; n < 4; n++)
            #pragma unroll
            for (int t = 0; t < 4; t++) acc[m][n][t] = 0.f;

    // global-load mapping: 4 float4 per thread per tile (128 rows x 8 quads)
    const int lrow[4] = { (tid + 0) >> 3, (tid + 256) >> 3, (tid + 512) >> 3, (tid + 768) >> 3 };
    const int lq   = tid & 7;

    float4 av[4], bv[4];
    auto load_chunk = [&](int k0) {
        #pragma unroll
        for (int i = 0; i < 4; i++) {
            const int r = lrow[i];
            bv[i] = *(const float4*)(W + (size_t)(colBase + r) * DD + k0 + lq * 4);
            const int gr = rowBase + r;
            if (gr < NN) {
                float4 a = *(const float4*)(A + (size_t)gr * DD + k0 + lq * 4);
                if (BN_IN) {
                    const float4 m4 = *(const float4*)(mu + k0 + lq * 4);
                    const float4 r4 = *(const float4*)(rs + k0 + lq * 4);
                    a.x = fmaxf((a.x - m4.x) * r4.x, 0.f);
                    a.y = fmaxf((a.y - m4.y) * r4.y, 0.f);
                    a.z = fmaxf((a.z - m4.z) * r4.z, 0.f);
                    a.w = fmaxf((a.w - m4.w) * r4.w, 0.f);
                }
                av[i] = a;
            } else {
                av[i] = make_float4(0.f, 0.f, 0.f, 0.f);
            }
        }
        // tf32 rounding on everything that feeds the MMA
        #pragma unroll
        for (int i = 0; i < 4; i++) {
            av[i].x = to_tf32(av[i].x); av[i].y = to_tf32(av[i].y);
            av[i].z = to_tf32(av[i].z); av[i].w = to_tf32(av[i].w);
            bv[i].x = to_tf32(bv[i].x); bv[i].y = to_tf32(bv[i].y);
            bv[i].z = to_tf32(bv[i].z); bv[i].w = to_tf32(bv[i].w);
        }
    };
    auto store_chunk = [&](int p) {
        float* As = smem + p * BUF_FL;
        float* Bs = smem + 2 * BUF_FL + p * BUF_FL;
        #pragma unroll
        for (int i = 0; i < 4; i++) {
            const int off = lrow[i] * SA + lq * 4;
            *(float4*)(As + off) = av[i];
            *(float4*)(Bs + off) = bv[i];
        }
    };

    load_chunk(0);
    store_chunk(0);
    __syncthreads();

    int p = 0;
    for (int c = 0; c < 16; ++c) {
        if (c < 15) load_chunk((c + 1) * 32);

        const uint32_t* As = (const uint32_t*)(smem + p * BUF_FL);
        const uint32_t* Bs = (const uint32_t*)(smem + 2 * BUF_FL + p * BUF_FL);
        #pragma unroll
        for (int ks = 0; ks < 4; ++ks) {
            const int kc = ks * 8;
            uint32_t af[4][4], bf[4][2];
            #pragma unroll
            for (int m = 0; m < 4; m++) {
                const int r0 = warpM * 64 + m * 16 + grp;
                af[m][0] = As[r0 * SA + kc + qd];
                af[m][1] = As[(r0 + 8) * SA + kc + qd];
                af[m][2] = As[r0 * SA + kc + qd + 4];
                af[m][3] = As[(r0 + 8) * SA + kc + qd + 4];
            }
            #pragma unroll
            for (int n = 0; n < 4; n++) {
                const int n0 = warpN * 32 + n * 8 + grp;
                bf[n][0] = Bs[n0 * SA + kc + qd];
                bf[n][1] = Bs[n0 * SA + kc + qd + 4];
            }
            #pragma unroll
            for (int m = 0; m < 4; m++)
                #pragma unroll
                for (int n = 0; n < 4; n++)
                    mma1688(acc[m][n], af[m], bf[n]);
        }

        if (c < 15) store_chunk(p ^ 1);
        __syncthreads();
        p ^= 1;
    }

    // ---- epilogue: v = acc*s[row] + bias[col]; store; optional col stats ----
    float psum[4][2], psq[4][2];
    #pragma unroll
    for (int n = 0; n < 4; n++) { psum[n][0] = psum[n][1] = 0.f; psq[n][0] = psq[n][1] = 0.f; }

    float2 bb[4];
    #pragma unroll
    for (int n = 0; n < 4; n++)
        bb[n] = *(const float2*)(bias + colBase + warpN * 32 + n * 8 + 2 * qd);

    #pragma unroll
    for (int m = 0; m < 4; m++) {
        const int r0 = rowBase + warpM * 64 + m * 16 + grp;
        const int r1 = r0 + 8;
        const bool ok0 = r0 < NN, ok1 = r1 < NN;
        const float s0 = ok0 ? g_s[r0] : 0.f;
        const float s1 = ok1 ? g_s[r1] : 0.f;
        #pragma unroll
        for (int n = 0; n < 4; n++) {
            const int col = colBase + warpN * 32 + n * 8 + 2 * qd;
            if (ok0) {
                const float v0 = fmaf(acc[m][n][0], s0, bb[n].x);
                const float v1 = fmaf(acc[m][n][1], s0, bb[n].y);
                *(float2*)(Y + (size_t)r0 * DD + col) = make_float2(v0, v1);
                if (STATS) {
                    psum[n][0] += v0; psum[n][1] += v1;
                    psq[n][0]  += v0 * v0; psq[n][1] += v1 * v1;
                }
            }
            if (ok1) {
                const float v2 = fmaf(acc[m][n][2], s1, bb[n].x);
                const float v3 = fmaf(acc[m][n][3], s1, bb[n].y);
                *(float2*)(Y + (size_t)r1 * DD + col) = make_float2(v2, v3);
                if (STATS) {
                    psum[n][0] += v2; psum[n][1] += v3;
                    psq[n][0]  += v2 * v2; psq[n][1] += v3 * v3;
                }
            }
        }
    }

    if (STATS) {
        #pragma unroll
        for (int n = 0; n < 4; n++)
            #pragma unroll
            for (int t = 0; t < 2; t++) {
                float a = psum[n][t], q = psq[n][t];
                #pragma unroll
                for (int off = 4; off < 32; off <<= 1) {
                    a += __shfl_xor_sync(0xFFFFFFFFu, a, off);
                    q += __shfl_xor_sync(0xFFFFFFFFu, q, off);
                }
                if (grp == 0) {
                    const int col = colBase + warpN * 32 + n * 8 + 2 * qd + t;
                    atomicAdd(&colsum[col], a);
                    atomicAdd(&colsq[col], q);
                }
            }
    }
}

// ---------------- launch ---------------------------------------------------
extern "C" void kernel_launch(void* const* d_in, const int* in_sizes, int n_in,
                              void* d_out, int out_size)
{
    const float* x  = (const float*)d_in[0];
    const int*   ei = (const int*)d_in[1];
    const float* W0 = (const float*)d_in[2];
    const float* b0 = (const float*)d_in[3];
    const float* W1 = (const float*)d_in[4];
    const float* b1 = (const float*)d_in[5];
    const float* W2 = (const float*)d_in[6];
    const float* b2 = (const float*)d_in[7];
    float* out = (float*)d_out;
    const int E = in_sizes[1] / 2;

    float *t1, *t2, *mu, *rs, *cs, *cq;
    cudaGetSymbolAddress((void**)&t1, g_t1);
    cudaGetSymbolAddress((void**)&t2, g_t2);
    cudaGetSymbolAddress((void**)&mu, g_mu);
    cudaGetSymbolAddress((void**)&rs, g_rs);
    cudaGetSymbolAddress((void**)&cs, g_colsum);
    cudaGetSymbolAddress((void**)&cq, g_colsq);

    cudaFuncSetAttribute(k_gemm<0,1>, cudaFuncAttributeMaxDynamicSharedMemorySize, SMEM_BYTES);
    cudaFuncSetAttribute(k_gemm<1,1>, cudaFuncAttributeMaxDynamicSharedMemorySize, SMEM_BYTES);
    cudaFuncSetAttribute(k_gemm<1,0>, cudaFuncAttributeMaxDynamicSharedMemorySize, SMEM_BYTES);

    const int ib = (NN + 255) / 256;
    const int eb = (E + 255) / 256;

    k_init<<<ib, 256>>>();
    k_deg<<<eb, 256>>>(ei, E);
    k_dinv<<<ib, 256>>>();
    k_s<<<eb, 256>>>(ei, E);

    dim3 grid(DD / 128, (NN + 127) / 128);
    k_gemm<0,1><<<grid, 256, SMEM_BYTES>>>(x,  W0, b0, t1, nullptr,  nullptr,  cs,      cq);
    k_bnstat<<<1, DD>>>(0);
    k_gemm<1,1><<<grid, 256, SMEM_BYTES>>>(t1, W1, b1, t2, mu,       rs,       cs + DD, cq + DD);
    k_bnstat<<<1, DD>>>(1);
    k_gemm<1,0><<<grid, 256, SMEM_BYTES>>>(t2, W2, b2, out, mu + DD, rs + DD,  nullptr, nullptr);
}

// round 15
// speedup vs baseline: 1.0019x; 1.0019x over previous
#include <cuda_runtime.h>
#include <cstdint>

#define NN    100000
#define DD    512
#define EPSBN 1e-5f

// smem: 2 buffers x (A 128x36 + B 128x36) floats
#define SA        36
#define BUF_FL    (128 * SA)
#define SMEM_FL   (4 * BUF_FL)
#define SMEM_BYTES (SMEM_FL * 4)

// ---------------- scratch (static device globals; no allocation) ----------
__device__ float g_t1[(size_t)NN * DD];
__device__ float g_t2[(size_t)NN * DD];
__device__ float g_deg[NN];
__device__ float g_dinv[NN];
__device__ float g_s[NN];
__device__ float g_colsum[2 * DD];
__device__ float g_colsq[2 * DD];
__device__ float g_mu[2 * DD];
__device__ float g_rs[2 * DD];

// ---------------- helpers ---------------------------------------------------
__device__ __forceinline__ float to_tf32(float x) {
    float r;
    asm("cvt.rna.tf32.f32 %0, %1;" : "=f"(r) : "f"(x));
    return r;
}
__device__ __forceinline__ void mma1688(float* c, const uint32_t* a, const uint32_t* b) {
    asm volatile(
        "mma.sync.aligned.m16n8k8.row.col.f32.tf32.tf32.f32 "
        "{%0,%1,%2,%3}, {%4,%5,%6,%7}, {%8,%9}, {%0,%1,%2,%3};"
        : "+f"(c[0]), "+f"(c[1]), "+f"(c[2]), "+f"(c[3])
        : "r"(a[0]), "r"(a[1]), "r"(a[2]), "r"(a[3]), "r"(b[0]), "r"(b[1]));
}

// ---------------- graph-scale kernels -------------------------------------
__global__ void k_init() {
    int i = blockIdx.x * blockDim.x + threadIdx.x;
    if (i < NN) g_deg[i] = 1.0f;
    if (i < 2 * DD) { g_colsum[i] = 0.f; g_colsq[i] = 0.f; }
}
__global__ void k_deg(const int* __restrict__ ei, int E) {
    int e = blockIdx.x * blockDim.x + threadIdx.x;
    if (e >= E) return;
    int s = ei[e], d = ei[E + e];
    if (s != d) atomicAdd(&g_deg[d], 1.0f);
}
__global__ void k_dinv() {
    int i = blockIdx.x * blockDim.x + threadIdx.x;
    if (i < NN) {
        float dg = g_deg[i];
        g_dinv[i] = rsqrtf(dg);
        g_s[i] = 1.0f / dg;
    }
}
__global__ void k_s(const int* __restrict__ ei, int E) {
    int e = blockIdx.x * blockDim.x + threadIdx.x;
    if (e >= E) return;
    int s = ei[e], d = ei[E + e];
    if (s != d) atomicAdd(&g_s[s], g_dinv[s] * g_dinv[d]);
}
__global__ void k_bnstat(int layer) {
    int c = threadIdx.x;
    float mu  = g_colsum[layer * DD + c] * (1.0f / NN);
    float var = g_colsq[layer * DD + c] * (1.0f / NN) - mu * mu;
    g_mu[layer * DD + c] = mu;
    g_rs[layer * DD + c] = rsqrtf(var + EPSBN);
}

// ---------------- tf32 mma.sync fused GEMM ---------------------------------
// Y[NN,512] = BNrelu?(A) @ W^T * s + b ; optional column sum/sumsq stats.
// CTA 128x128, K-chunk 32, double-buffered smem, 8 warps (2M x 4N), warp 64x32.
template <int BN_IN, int STATS>
__global__ void __launch_bounds__(256, 1)
k_gemm(const float* __restrict__ A, const float* __restrict__ W,
       const float* __restrict__ bias, float* __restrict__ Y,
       const float* __restrict__ mu, const float* __restrict__ rs,
       float* __restrict__ colsum, float* __restrict__ colsq)
{
    extern __shared__ float smem[];
    // buffer p: A at p*BUF_FL, B at 2*BUF_FL + p*BUF_FL

    const int tid  = threadIdx.x;
    const int lane = tid & 31;
    const int warpId = tid >> 5;
    const int warpM = warpId & 1;        // 0..1  (64-row band)
    const int warpN = warpId >> 1;       // 0..3  (32-col band)
    const int grp = lane >> 2;           // 0..7
    const int qd  = lane & 3;            // 0..3
    const int rowBase = blockIdx.y * 128;
    const int colBase = blockIdx.x * 128;

    float acc[4][4][4];
    #pragma unroll
    for (int m = 0; m < 4; m++)
        #pragma unroll
        for (int n = 0; n < 4; n++)
            #pragma unroll
            for (int t = 0; t < 4; t++) acc[m][n][t] = 0.f;

    // global-load mapping: 4 float4 per thread per tile (128 rows x 8 quads)
    const int lrow[4] = { (tid + 0) >> 3, (tid + 256) >> 3, (tid + 512) >> 3, (tid + 768) >> 3 };
    const int lq   = tid & 7;

    float4 av[4], bv[4];
    auto load_chunk = [&](int k0) {
        #pragma unroll
        for (int i = 0; i < 4; i++) {
            const int r = lrow[i];
            bv[i] = *(const float4*)(W + (size_t)(colBase + r) * DD + k0 + lq * 4);
            const int gr = rowBase + r;
            if (gr < NN) {
                float4 a = *(const float4*)(A + (size_t)gr * DD + k0 + lq * 4);
                if (BN_IN) {
                    const float4 m4 = *(const float4*)(mu + k0 + lq * 4);
                    const float4 r4 = *(const float4*)(rs + k0 + lq * 4);
                    a.x = fmaxf((a.x - m4.x) * r4.x, 0.f);
                    a.y = fmaxf((a.y - m4.y) * r4.y, 0.f);
                    a.z = fmaxf((a.z - m4.z) * r4.z, 0.f);
                    a.w = fmaxf((a.w - m4.w) * r4.w, 0.f);
                }
                av[i] = a;
            } else {
                av[i] = make_float4(0.f, 0.f, 0.f, 0.f);
            }
        }
        // tf32 rounding on everything that feeds the MMA
        #pragma unroll
        for (int i = 0; i < 4; i++) {
            av[i].x = to_tf32(av[i].x); av[i].y = to_tf32(av[i].y);
            av[i].z = to_tf32(av[i].z); av[i].w = to_tf32(av[i].w);
            bv[i].x = to_tf32(bv[i].x); bv[i].y = to_tf32(bv[i].y);
            bv[i].z = to_tf32(bv[i].z); bv[i].w = to_tf32(bv[i].w);
        }
    };
    auto store_chunk = [&](int p) {
        float* As = smem + p * BUF_FL;
        float* Bs = smem + 2 * BUF_FL + p * BUF_FL;
        #pragma unroll
        for (int i = 0; i < 4; i++) {
            const int off = lrow[i] * SA + lq * 4;
            *(float4*)(As + off) = av[i];
            *(float4*)(Bs + off) = bv[i];
        }
    };

    load_chunk(0);
    store_chunk(0);
    __syncthreads();

    int p = 0;
    for (int c = 0; c < 16; ++c) {
        if (c < 15) load_chunk((c + 1) * 32);

        const uint32_t* As = (const uint32_t*)(smem + p * BUF_FL);
        const uint32_t* Bs = (const uint32_t*)(smem + 2 * BUF_FL + p * BUF_FL);
        #pragma unroll
        for (int ks = 0; ks < 4; ++ks) {
            const int kc = ks * 8;
            uint32_t af[4][4], bf[4][2];
            #pragma unroll
            for (int m = 0; m < 4; m++) {
                const int r0 = warpM * 64 + m * 16 + grp;
                af[m][0] = As[r0 * SA + kc + qd];
                af[m][1] = As[(r0 + 8) * SA + kc + qd];
                af[m][2] = As[r0 * SA + kc + qd + 4];
                af[m][3] = As[(r0 + 8) * SA + kc + qd + 4];
            }
            #pragma unroll
            for (int n = 0; n < 4; n++) {
                const int n0 = warpN * 32 + n * 8 + grp;
                bf[n][0] = Bs[n0 * SA + kc + qd];
                bf[n][1] = Bs[n0 * SA + kc + qd + 4];
            }
            #pragma unroll
            for (int m = 0; m < 4; m++)
                #pragma unroll
                for (int n = 0; n < 4; n++)
                    mma1688(acc[m][n], af[m], bf[n]);
        }

        if (c < 15) store_chunk(p ^ 1);
        __syncthreads();
        p ^= 1;
    }

    // ---- epilogue: v = acc*s[row] + bias[col]; store; optional col stats ----
    float psum[4][2], psq[4][2];
    #pragma unroll
    for (int n = 0; n < 4; n++) { psum[n][0] = psum[n][1] = 0.f; psq[n][0] = psq[n][1] = 0.f; }

    float2 bb[4];
    #pragma unroll
    for (int n = 0; n < 4; n++)
        bb[n] = *(const float2*)(bias + colBase + warpN * 32 + n * 8 + 2 * qd);

    #pragma unroll
    for (int m = 0; m < 4; m++) {
        const int r0 = rowBase + warpM * 64 + m * 16 + grp;
        const int r1 = r0 + 8;
        const bool ok0 = r0 < NN, ok1 = r1 < NN;
        const float s0 = ok0 ? g_s[r0] : 0.f;
        const float s1 = ok1 ? g_s[r1] : 0.f;
        #pragma unroll
        for (int n = 0; n < 4; n++) {
            const int col = colBase + warpN * 32 + n * 8 + 2 * qd;
            if (ok0) {
                const float v0 = fmaf(acc[m][n][0], s0, bb[n].x);
                const float v1 = fmaf(acc[m][n][1], s0, bb[n].y);
                *(float2*)(Y + (size_t)r0 * DD + col) = make_float2(v0, v1);
                if (STATS) {
                    psum[n][0] += v0; psum[n][1] += v1;
                    psq[n][0]  += v0 * v0; psq[n][1] += v1 * v1;
                }
            }
            if (ok1) {
                const float v2 = fmaf(acc[m][n][2], s1, bb[n].x);
                const float v3 = fmaf(acc[m][n][3], s1, bb[n].y);
                *(float2*)(Y + (size_t)r1 * DD + col) = make_float2(v2, v3);
                if (STATS) {
                    psum[n][0] += v2; psum[n][1] += v3;
                    psq[n][0]  += v2 * v2; psq[n][1] += v3 * v3;
                }
            }
        }
    }

    if (STATS) {
        #pragma unroll
        for (int n = 0; n < 4; n++)
            #pragma unroll
            for (int t = 0; t < 2; t++) {
                float a = psum[n][t], q = psq[n][t];
                #pragma unroll
                for (int off = 4; off < 32; off <<= 1) {
                    a += __shfl_xor_sync(0xFFFFFFFFu, a, off);
                    q += __shfl_xor_sync(0xFFFFFFFFu, q, off);
                }
                if (grp == 0) {
                    const int col = colBase + warpN * 32 + n * 8 + 2 * qd + t;
                    atomicAdd(&colsum[col], a);
                    atomicAdd(&colsq[col], q);
                }
            }
    }
}

// ---------------- launch ---------------------------------------------------
extern "C" void kernel_launch(void* const* d_in, const int* in_sizes, int n_in,
                              void* d_out, int out_size)
{
    const float* x  = (const float*)d_in[0];
    const int*   ei = (const int*)d_in[1];
    const float* W0 = (const float*)d_in[2];
    const float* b0 = (const float*)d_in[3];
    const float* W1 = (const float*)d_in[4];
    const float* b1 = (const float*)d_in[5];
    const float* W2 = (const float*)d_in[6];
    const float* b2 = (const float*)d_in[7];
    float* out = (float*)d_out;
    const int E = in_sizes[1] / 2;

    float *t1, *t2, *mu, *rs, *cs, *cq;
    cudaGetSymbolAddress((void**)&t1, g_t1);
    cudaGetSymbolAddress((void**)&t2, g_t2);
    cudaGetSymbolAddress((void**)&mu, g_mu);
    cudaGetSymbolAddress((void**)&rs, g_rs);
    cudaGetSymbolAddress((void**)&cs, g_colsum);
    cudaGetSymbolAddress((void**)&cq, g_colsq);

    cudaFuncSetAttribute(k_gemm<0,1>, cudaFuncAttributeMaxDynamicSharedMemorySize, SMEM_BYTES);
    cudaFuncSetAttribute(k_gemm<1,1>, cudaFuncAttributeMaxDynamicSharedMemorySize, SMEM_BYTES);
    cudaFuncSetAttribute(k_gemm<1,0>, cudaFuncAttributeMaxDynamicSharedMemorySize, SMEM_BYTES);

    const int ib = (NN + 255) / 256;
    const int eb = (E + 255) / 256;

    k_init<<<ib, 256>>>();
    k_deg<<<eb, 256>>>(ei, E);
    k_dinv<<<ib, 256>>>();
    k_s<<<eb, 256>>>(ei, E);

    dim3 grid(DD / 128, (NN + 127) / 128);
    k_gemm<0,1><<<grid, 256, SMEM_BYTES>>>(x,  W0, b0, t1, nullptr,  nullptr,  cs,      cq);
    k_bnstat<<<1, DD>>>(0);
    k_gemm<1,1><<<grid, 256, SMEM_BYTES>>>(t1, W1, b1, t2, mu,       rs,       cs + DD, cq + DD);
    k_bnstat<<<1, DD>>>(1);
    k_gemm<1,0><<<grid, 256, SMEM_BYTES>>>(t2, W2, b2, out, mu + DD, rs + DD,  nullptr, nullptr);
}